// round 3
// baseline (speedup 1.0000x reference)
#include <cuda_runtime.h>
#include <math.h>

// Problem dims (fixed by the registry problem)
#define Bn 8
#define Tn 1024
#define Dn 512
#define Hn 1024
#define En 8
#define Kn 2
#define Nn (Bn * Tn)          // 8192 tokens
#define LOG_2PI 1.8378770664093453f

// ---------------- scratch (static __device__ globals; no allocs) ------------
__device__ float g_h[(size_t)Nn * Kn * Hn];   // 64 MB: GELU activations per (token,slot)
__device__ float g_gate[Nn * Kn];             // gate weight per (token,slot)
__device__ int   g_counts[En];                // tokens routed per expert
__device__ int   g_list[En][Nn];              // entry = (token<<1)|slot, per expert
__device__ float g_isig[Bn * En * Dn];        // exp(-log_sigma)
__device__ float g_sumls[Bn * En];            // sum_d log_sigma

// ---------------- kernel 0: zero y region + routing counters ---------------
__global__ void zero_kernel(float* __restrict__ y) {
    int i = blockIdx.x * blockDim.x + threadIdx.x;
    if (i < Nn * Dn) y[i] = 0.0f;
    if (blockIdx.x == 0 && threadIdx.x < En) g_counts[threadIdx.x] = 0;
}

// ---------------- kernel 1: precompute inv_sigma and sum(log_sigma) --------
__global__ void precompute_kernel(const float* __restrict__ log_sigmas) {
    int be = blockIdx.x;              // b*En + e, 64 blocks
    int tid = threadIdx.x;            // 256 threads
    __shared__ float red[256];
    float s = 0.0f;
    for (int d = tid; d < Dn; d += 256) {
        float ls = log_sigmas[be * Dn + d];
        g_isig[be * Dn + d] = __expf(-ls);
        s += ls;
    }
    red[tid] = s;
    __syncthreads();
    for (int o = 128; o > 0; o >>= 1) {
        if (tid < o) red[tid] += red[tid + o];
        __syncthreads();
    }
    if (tid == 0) g_sumls[be] = red[0];
}

// ---------------- kernel 2: gating (one warp per token) --------------------
__global__ void gate_kernel(const float* __restrict__ x,
                            const float* __restrict__ mus,
                            float* __restrict__ out_lp,
                            float* __restrict__ out_ti,
                            int has_lp, int has_ti) {
    int warp = threadIdx.x >> 5;
    int lane = threadIdx.x & 31;
    int t = blockIdx.x * 8 + warp;
    if (t >= Nn) return;
    int b = t / Tn;

    float xr[16];
#pragma unroll
    for (int i = 0; i < 16; i++) xr[i] = x[t * Dn + lane + 32 * i];

    float lp[En];
#pragma unroll
    for (int e = 0; e < En; e++) {
        const float* mu = mus + (b * En + e) * Dn;
        const float* is = g_isig + (b * En + e) * Dn;
        float a = 0.0f;
#pragma unroll
        for (int i = 0; i < 16; i++) {
            float z = (xr[i] - mu[lane + 32 * i]) * is[lane + 32 * i];
            a = fmaf(z, z, a);
        }
#pragma unroll
        for (int o = 16; o > 0; o >>= 1) a += __shfl_xor_sync(0xffffffffu, a, o);
        lp[e] = -0.5f * a - g_sumls[b * En + e] - 0.5f * LOG_2PI * (float)Dn;
    }

    if (lane == 0) {
        // top-2 with jax.lax.top_k tie order (lowest index wins on ties)
        int e0 = 0;
#pragma unroll
        for (int e = 1; e < En; e++) if (lp[e] > lp[e0]) e0 = e;
        int e1 = -1;
#pragma unroll
        for (int e = 0; e < En; e++) {
            if (e == e0) continue;
            if (e1 < 0 || lp[e] > lp[e1]) e1 = e;
        }
        float p1 = __expf(lp[e1] - lp[e0]);    // lp[e0] >= lp[e1]
        float inv = 1.0f / (1.0f + p1);
        g_gate[t * 2 + 0] = inv;
        g_gate[t * 2 + 1] = p1 * inv;

        int p = atomicAdd(&g_counts[e0], 1);
        g_list[e0][p] = (t << 1) | 0;
        p = atomicAdd(&g_counts[e1], 1);
        g_list[e1][p] = (t << 1) | 1;

        if (has_lp) {
#pragma unroll
            for (int e = 0; e < En; e++) out_lp[t * En + e] = lp[e];
        }
        if (has_ti) {
            out_ti[t * 2 + 0] = (float)e0;
            out_ti[t * 2 + 1] = (float)e1;
        }
    }
}

// ---------------- kernel 3: GEMM1  h = gelu(Xg @ W1[e] + b1[e]) ------------
// 128(tokens) x 64(H) tile, K=16 steps, 256 threads, 8x4 micro-tile
__global__ __launch_bounds__(256) void gemm1_kernel(const float* __restrict__ x,
                                                    const float* __restrict__ W1,
                                                    const float* __restrict__ b1) {
    int e = blockIdx.z;
    int cnt = g_counts[e];
    int row0 = blockIdx.y * 128;
    if (row0 >= cnt) return;
    int n0 = blockIdx.x * 64;

    __shared__ float As[16][132];  // [k][m], pad 132 keeps float4 alignment
    __shared__ float Bs[16][64];   // [k][n]
    __shared__ int ent[128];

    int tid = threadIdx.x;
    if (tid < 128) ent[tid] = (row0 + tid < cnt) ? g_list[e][row0 + tid] : -1;
    __syncthreads();

    int tx = tid & 15, ty = tid >> 4;   // tx: 16 col-groups of 4, ty: 16 row-groups of 8
    float acc[8][4];
#pragma unroll
    for (int i = 0; i < 8; i++)
#pragma unroll
        for (int j = 0; j < 4; j++) acc[i][j] = 0.0f;

    const float* Wb = W1 + (size_t)e * Dn * Hn;

    for (int k0 = 0; k0 < Dn; k0 += 16) {
#pragma unroll
        for (int i = tid; i < 2048; i += 256) {   // A: 128 rows x 16 k
            int m = i >> 4, k = i & 15;
            int en = ent[m];
            As[k][m] = (en >= 0) ? x[(size_t)(en >> 1) * Dn + k0 + k] : 0.0f;
        }
#pragma unroll
        for (int i = tid; i < 1024; i += 256) {   // B: 16 k x 64 n
            int k = i >> 6, n = i & 63;
            Bs[k][n] = Wb[(size_t)(k0 + k) * Hn + n0 + n];
        }
        __syncthreads();
#pragma unroll
        for (int k = 0; k < 16; k++) {
            float4 a0 = *(const float4*)&As[k][ty * 8];
            float4 a1 = *(const float4*)&As[k][ty * 8 + 4];
            float4 bb = *(const float4*)&Bs[k][tx * 4];
            float av[8] = {a0.x, a0.y, a0.z, a0.w, a1.x, a1.y, a1.z, a1.w};
            float bv[4] = {bb.x, bb.y, bb.z, bb.w};
#pragma unroll
            for (int i = 0; i < 8; i++)
#pragma unroll
                for (int j = 0; j < 4; j++) acc[i][j] = fmaf(av[i], bv[j], acc[i][j]);
        }
        __syncthreads();
    }

#pragma unroll
    for (int i = 0; i < 8; i++) {
        int m = ty * 8 + i;
        int en = ent[m];
        if (en < 0) continue;
#pragma unroll
        for (int j = 0; j < 4; j++) {
            int n = n0 + tx * 4 + j;
            float v = acc[i][j] + b1[e * Hn + n];
            float g = 0.5f * v * (1.0f + erff(v * 0.7071067811865476f));
            g_h[(size_t)en * Hn + n] = g;
        }
    }
}

// ---------------- kernel 4: GEMM2  y += gate*(h @ W2[e] + b2[e]) -----------
__global__ __launch_bounds__(256) void gemm2_kernel(const float* __restrict__ W2,
                                                    const float* __restrict__ b2,
                                                    float* __restrict__ y) {
    int e = blockIdx.z;
    int cnt = g_counts[e];
    int row0 = blockIdx.y * 128;
    if (row0 >= cnt) return;
    int n0 = blockIdx.x * 64;   // D tile

    __shared__ float As[16][132];
    __shared__ float Bs[16][64];
    __shared__ int ent[128];
    __shared__ float gw[128];

    int tid = threadIdx.x;
    if (tid < 128) {
        int en = (row0 + tid < cnt) ? g_list[e][row0 + tid] : -1;
        ent[tid] = en;
        gw[tid] = (en >= 0) ? g_gate[en] : 0.0f;
    }
    __syncthreads();

    int tx = tid & 15, ty = tid >> 4;
    float acc[8][4];
#pragma unroll
    for (int i = 0; i < 8; i++)
#pragma unroll
        for (int j = 0; j < 4; j++) acc[i][j] = 0.0f;

    const float* Wb = W2 + (size_t)e * Hn * Dn;

    for (int k0 = 0; k0 < Hn; k0 += 16) {
#pragma unroll
        for (int i = tid; i < 2048; i += 256) {
            int m = i >> 4, k = i & 15;
            int en = ent[m];
            As[k][m] = (en >= 0) ? g_h[(size_t)en * Hn + k0 + k] : 0.0f;
        }
#pragma unroll
        for (int i = tid; i < 1024; i += 256) {
            int k = i >> 6, n = i & 63;
            Bs[k][n] = Wb[(size_t)(k0 + k) * Dn + n0 + n];
        }
        __syncthreads();
#pragma unroll
        for (int k = 0; k < 16; k++) {
            float4 a0 = *(const float4*)&As[k][ty * 8];
            float4 a1 = *(const float4*)&As[k][ty * 8 + 4];
            float4 bb = *(const float4*)&Bs[k][tx * 4];
            float av[8] = {a0.x, a0.y, a0.z, a0.w, a1.x, a1.y, a1.z, a1.w};
            float bv[4] = {bb.x, bb.y, bb.z, bb.w};
#pragma unroll
            for (int i = 0; i < 8; i++)
#pragma unroll
                for (int j = 0; j < 4; j++) acc[i][j] = fmaf(av[i], bv[j], acc[i][j]);
        }
        __syncthreads();
    }

#pragma unroll
    for (int i = 0; i < 8; i++) {
        int m = ty * 8 + i;
        int en = ent[m];
        if (en < 0) continue;
        float g = gw[m];
        int t = en >> 1;
#pragma unroll
        for (int j = 0; j < 4; j++) {
            int n = n0 + tx * 4 + j;
            float v = (acc[i][j] + b2[e * Dn + n]) * g;
            atomicAdd(&y[(size_t)t * Dn + n], v);
        }
    }
}

// ---------------- launch --------------------------------------------------
extern "C" void kernel_launch(void* const* d_in, const int* in_sizes, int n_in,
                              void* d_out, int out_size) {
    const float* x   = (const float*)d_in[0];
    const float* mus = (const float*)d_in[1];
    const float* ls  = (const float*)d_in[2];
    const float* W1  = (const float*)d_in[3];
    const float* b1  = (const float*)d_in[4];
    const float* W2  = (const float*)d_in[5];
    const float* b2  = (const float*)d_in[6];
    float* out = (float*)d_out;

    const int Ny  = Nn * Dn;   // y elements
    const int Nlp = Nn * En;   // log_probs elements
    const int Nti = Nn * Kn;   // top_idx elements
    int has_lp = (out_size >= Ny + Nlp) ? 1 : 0;
    int has_ti = (out_size >= Ny + Nlp + Nti) ? 1 : 0;
    float* out_lp = out + Ny;
    float* out_ti = out + Ny + Nlp;

    zero_kernel<<<(Ny + 255) / 256, 256>>>(out);
    precompute_kernel<<<Bn * En, 256>>>(ls);
    gate_kernel<<<Nn / 8, 256>>>(x, mus, out_lp, out_ti, has_lp, has_ti);

    dim3 g1(Hn / 64, Nn / 128, En);   // (16, 64, 8); early-exit beyond counts
    gemm1_kernel<<<g1, 256>>>(x, W1, b1);

    dim3 g2(Dn / 64, Nn / 128, En);   // (8, 64, 8)
    gemm2_kernel<<<g2, 256>>>(W2, b2, out);
    (void)in_sizes; (void)n_in;
}

// round 5
// speedup vs baseline: 2.8577x; 2.8577x over previous
#include <cuda_runtime.h>
#include <cuda_bf16.h>
#include <math.h>
#include <stdint.h>

// Problem dims
#define Bn 8
#define Tn 1024
#define Dn 512
#define Hn 1024
#define En 8
#define Kn 2
#define Nn (Bn * Tn)          // 8192 tokens
#define LOG_2PI 1.8378770664093453f

// ---------------- scratch (static __device__ globals) ----------------------
__device__ __nv_bfloat16 g_hh[(size_t)Nn * Kn * Hn];   // gelu(h) hi, [slot][H]
__device__ __nv_bfloat16 g_hl[(size_t)Nn * Kn * Hn];   // gelu(h) lo
__device__ float g_out[(size_t)Nn * Kn * Dn];          // per-slot gated outputs
__device__ float g_gate[Nn * Kn];
__device__ int   g_counts[En];
__device__ int   g_list[En][Nn];
__device__ float g_isig[Bn * En * Dn];
__device__ float g_sumls[Bn * En];
__device__ __nv_bfloat16 g_w1h[(size_t)En * Hn * Dn];  // W1^T [E][H][D] hi
__device__ __nv_bfloat16 g_w1l[(size_t)En * Hn * Dn];
__device__ __nv_bfloat16 g_w2h[(size_t)En * Dn * Hn];  // W2^T [E][D][H] hi
__device__ __nv_bfloat16 g_w2l[(size_t)En * Dn * Hn];

// ---------------- helpers ---------------------------------------------------
__device__ __forceinline__ uint32_t smem_u32(const void* p) {
    uint32_t a;
    asm("{ .reg .u64 t; cvta.to.shared.u64 t, %1; cvt.u32.u64 %0, t; }" : "=r"(a) : "l"(p));
    return a;
}
__device__ __forceinline__ void ldsm4(uint32_t* r, uint32_t addr) {
    asm volatile("ldmatrix.sync.aligned.m8n8.x4.shared.b16 {%0,%1,%2,%3}, [%4];"
        : "=r"(r[0]), "=r"(r[1]), "=r"(r[2]), "=r"(r[3]) : "r"(addr));
}
__device__ __forceinline__ void mma16816(float* c, const uint32_t* a, const uint32_t* b) {
    asm volatile("mma.sync.aligned.m16n8k16.row.col.f32.bf16.bf16.f32 "
        "{%0,%1,%2,%3}, {%4,%5,%6,%7}, {%8,%9}, {%0,%1,%2,%3};"
        : "+f"(c[0]), "+f"(c[1]), "+f"(c[2]), "+f"(c[3])
        : "r"(a[0]), "r"(a[1]), "r"(a[2]), "r"(a[3]), "r"(b[0]), "r"(b[1]));
}
__device__ __forceinline__ void split2(float v, __nv_bfloat16& h, __nv_bfloat16& l) {
    h = __float2bfloat16(v);
    l = __float2bfloat16(v - __bfloat162float(h));
}

// ---------------- kernel: precompute isig/sumls + zero counts --------------
__global__ void precompute_kernel(const float* __restrict__ log_sigmas) {
    int be = blockIdx.x;
    int tid = threadIdx.x;
    if (be == 0 && tid < En) g_counts[tid] = 0;
    __shared__ float red[256];
    float s = 0.0f;
    for (int d = tid; d < Dn; d += 256) {
        float ls = log_sigmas[be * Dn + d];
        g_isig[be * Dn + d] = __expf(-ls);
        s += ls;
    }
    red[tid] = s;
    __syncthreads();
    for (int o = 128; o > 0; o >>= 1) {
        if (tid < o) red[tid] += red[tid + o];
        __syncthreads();
    }
    if (tid == 0) g_sumls[be] = red[0];
}

// ---------------- kernel: transpose + bf16 hi/lo split ---------------------
// src [E][R][C] -> dst [E][C][R]
__global__ void transpose_split_kernel(const float* __restrict__ src,
                                       __nv_bfloat16* __restrict__ dhi,
                                       __nv_bfloat16* __restrict__ dlo,
                                       int R, int C) {
    __shared__ float t[32][33];
    int e = blockIdx.z;
    int c0 = blockIdx.x * 32, r0 = blockIdx.y * 32;
    int tx = threadIdx.x & 31, ty = threadIdx.x >> 5;
    const float* s = src + (size_t)e * R * C;
#pragma unroll
    for (int p = 0; p < 4; p++)
        t[ty + p * 8][tx] = s[(size_t)(r0 + ty + p * 8) * C + c0 + tx];
    __syncthreads();
#pragma unroll
    for (int p = 0; p < 4; p++) {
        float v = t[tx][ty + p * 8];
        __nv_bfloat16 hi, lo;
        split2(v, hi, lo);
        size_t o = (size_t)e * C * R + (size_t)(c0 + ty + p * 8) * R + r0 + tx;
        dhi[o] = hi;
        dlo[o] = lo;
    }
}

// ---------------- kernel: gating (one warp per token) ----------------------
__global__ void gate_kernel(const float* __restrict__ x,
                            const float* __restrict__ mus,
                            float* __restrict__ out_lp,
                            float* __restrict__ out_ti,
                            int has_lp, int has_ti) {
    int warp = threadIdx.x >> 5;
    int lane = threadIdx.x & 31;
    int t = blockIdx.x * 8 + warp;
    if (t >= Nn) return;
    int b = t / Tn;

    float xr[16];
#pragma unroll
    for (int i = 0; i < 16; i++) xr[i] = x[t * Dn + lane + 32 * i];

    float lp[En];
#pragma unroll
    for (int e = 0; e < En; e++) {
        const float* mu = mus + (b * En + e) * Dn;
        const float* is = g_isig + (b * En + e) * Dn;
        float a = 0.0f;
#pragma unroll
        for (int i = 0; i < 16; i++) {
            float z = (xr[i] - mu[lane + 32 * i]) * is[lane + 32 * i];
            a = fmaf(z, z, a);
        }
#pragma unroll
        for (int o = 16; o > 0; o >>= 1) a += __shfl_xor_sync(0xffffffffu, a, o);
        lp[e] = -0.5f * a - g_sumls[b * En + e] - 0.5f * LOG_2PI * (float)Dn;
    }

    if (lane == 0) {
        int e0 = 0;
#pragma unroll
        for (int e = 1; e < En; e++) if (lp[e] > lp[e0]) e0 = e;
        int e1 = -1;
#pragma unroll
        for (int e = 0; e < En; e++) {
            if (e == e0) continue;
            if (e1 < 0 || lp[e] > lp[e1]) e1 = e;
        }
        float p1 = __expf(lp[e1] - lp[e0]);
        float inv = 1.0f / (1.0f + p1);
        g_gate[t * 2 + 0] = inv;
        g_gate[t * 2 + 1] = p1 * inv;
        int p = atomicAdd(&g_counts[e0], 1);
        g_list[e0][p] = (t << 1) | 0;
        p = atomicAdd(&g_counts[e1], 1);
        g_list[e1][p] = (t << 1) | 1;
        if (has_lp) {
#pragma unroll
            for (int e = 0; e < En; e++) out_lp[t * En + e] = lp[e];
        }
        if (has_ti) {
            out_ti[t * 2 + 0] = (float)e0;
            out_ti[t * 2 + 1] = (float)e1;
        }
    }
}

// ---------------- warp-MMA grouped GEMM ------------------------------------
// CTA 128x128, 8 warps (warp tile 32x64), K-step 32, 3-term bf16 split.
// MODE 0: h = gelu(Xg @ W1T + b1) -> (g_hh, g_hl) bf16 pairs. A=x fp32, K=512, N=1024.
// MODE 1: g_out = gate*(h @ W2T + b2). A = (g_hh,g_hl), K=1024, N=512.
#define ROWB 80   // smem row stride in bytes (64 data + 16 pad): conflict-free ldmatrix
template <int MODE>
__global__ __launch_bounds__(256) void gemm_mma(const float* __restrict__ Af,
                                                const __nv_bfloat16* __restrict__ Abh,
                                                const __nv_bfloat16* __restrict__ Abl,
                                                const __nv_bfloat16* __restrict__ Bhg,
                                                const __nv_bfloat16* __restrict__ Blg,
                                                const float* __restrict__ bias,
                                                float* __restrict__ outf,
                                                __nv_bfloat16* __restrict__ outh,
                                                __nv_bfloat16* __restrict__ outl) {
    constexpr int Ktot = MODE ? Hn : Dn;
    constexpr int Ntot = MODE ? Dn : Hn;

    int e = blockIdx.z;
    int cnt = g_counts[e];
    int row0 = blockIdx.y * 128;
    if (row0 >= cnt) return;
    int n0 = blockIdx.x * 128;

    __shared__ __align__(16) char sA[2][128 * ROWB];  // hi, lo
    __shared__ __align__(16) char sB[2][128 * ROWB];
    __shared__ int ent[128];
    __shared__ float gw[128];

    int tid = threadIdx.x, lane = tid & 31, wid = tid >> 5;
    int warp_m = wid & 3, warp_n = wid >> 2;     // 4 x 2 warps

    if (tid < 128) {
        int en = (row0 + tid < cnt) ? g_list[e][row0 + tid] : -1;
        ent[tid] = en;
        gw[tid] = (en >= 0) ? g_gate[en] : 0.0f;
    }
    __syncthreads();

    const __nv_bfloat16* Bhe = Bhg + (size_t)e * Ntot * Ktot + (size_t)n0 * Ktot;
    const __nv_bfloat16* Ble = Blg + (size_t)e * Ntot * Ktot + (size_t)n0 * Ktot;

    uint32_t sA_hi = smem_u32(sA[0]), sA_lo = smem_u32(sA[1]);
    uint32_t sB_hi = smem_u32(sB[0]), sB_lo = smem_u32(sB[1]);

    float c[2][8][4];
#pragma unroll
    for (int i = 0; i < 2; i++)
#pragma unroll
        for (int j = 0; j < 8; j++)
#pragma unroll
            for (int q = 0; q < 4; q++) c[i][j][q] = 0.0f;

    // precomputed ldmatrix lane addresses (offsets within tile)
    // A x4: lanes 0-15 -> rows 0-15 @k0 ; lanes 16-31 -> rows 0-15 @k8
    uint32_t a_row = (uint32_t)(lane & 15);
    uint32_t a_kh  = (uint32_t)((lane >> 4) << 3);
    // B x4: lanes0-7: n0-7@k0; 8-15: n0-7@k8; 16-23: n8-15@k0; 24-31: n8-15@k8
    uint32_t b_row = (uint32_t)((lane & 7) + ((lane >> 4) << 3));
    uint32_t b_kh  = (uint32_t)(lane & 8);

    for (int k0 = 0; k0 < Ktot; k0 += 32) {
        // ---- fill A tile (128 x 32) hi/lo ----
        if (MODE == 0) {
            for (int i = tid; i < 1024; i += 256) {     // 8 float4 per row
                int m = i >> 3, c4 = (i & 7) * 4;
                int en = ent[m];
                float4 v = make_float4(0.f, 0.f, 0.f, 0.f);
                if (en >= 0) v = *(const float4*)(Af + (size_t)(en >> 1) * Dn + k0 + c4);
                __nv_bfloat16 h0, l0, h1, l1, h2, l2, h3, l3;
                split2(v.x, h0, l0); split2(v.y, h1, l1);
                split2(v.z, h2, l2); split2(v.w, h3, l3);
                unsigned long long ph = (unsigned long long)__bfloat16_as_ushort(h0)
                    | ((unsigned long long)__bfloat16_as_ushort(h1) << 16)
                    | ((unsigned long long)__bfloat16_as_ushort(h2) << 32)
                    | ((unsigned long long)__bfloat16_as_ushort(h3) << 48);
                unsigned long long pl = (unsigned long long)__bfloat16_as_ushort(l0)
                    | ((unsigned long long)__bfloat16_as_ushort(l1) << 16)
                    | ((unsigned long long)__bfloat16_as_ushort(l2) << 32)
                    | ((unsigned long long)__bfloat16_as_ushort(l3) << 48);
                *(unsigned long long*)(sA[0] + m * ROWB + c4 * 2) = ph;
                *(unsigned long long*)(sA[1] + m * ROWB + c4 * 2) = pl;
            }
        } else {
            for (int i = tid; i < 512; i += 256) {      // 4 x 16B per row
                int m = i >> 2, k8 = (i & 3) * 8;
                int en = ent[m];
                uint4 vh = make_uint4(0, 0, 0, 0), vl = make_uint4(0, 0, 0, 0);
                if (en >= 0) {
                    vh = *(const uint4*)(Abh + (size_t)en * Hn + k0 + k8);
                    vl = *(const uint4*)(Abl + (size_t)en * Hn + k0 + k8);
                }
                *(uint4*)(sA[0] + m * ROWB + k8 * 2) = vh;
                *(uint4*)(sA[1] + m * ROWB + k8 * 2) = vl;
            }
        }
        // ---- fill B tile (128 x 32) hi/lo ----
        for (int i = tid; i < 512; i += 256) {
            int n = i >> 2, k8 = (i & 3) * 8;
            uint4 vh = *(const uint4*)(Bhe + (size_t)n * Ktot + k0 + k8);
            uint4 vl = *(const uint4*)(Ble + (size_t)n * Ktot + k0 + k8);
            *(uint4*)(sB[0] + n * ROWB + k8 * 2) = vh;
            *(uint4*)(sB[1] + n * ROWB + k8 * 2) = vl;
        }
        __syncthreads();

        // ---- compute: two k16 halves ----
#pragma unroll
        for (int kk = 0; kk < 2; kk++) {
            uint32_t kbyte = (uint32_t)(kk * 32) + a_kh * 2;
            uint32_t ah[2][4], al[2][4];
#pragma unroll
            for (int mt = 0; mt < 2; mt++) {
                uint32_t ro = (uint32_t)(warp_m * 32 + mt * 16) + a_row;
                ldsm4(ah[mt], sA_hi + ro * ROWB + kbyte);
                ldsm4(al[mt], sA_lo + ro * ROWB + kbyte);
            }
            uint32_t kbyteb = (uint32_t)(kk * 32) + b_kh * 2;
            uint32_t bh[8][2], bl[8][2];
#pragma unroll
            for (int p = 0; p < 4; p++) {
                uint32_t ro = (uint32_t)(warp_n * 64 + p * 16) + b_row;
                uint32_t r4[4];
                ldsm4(r4, sB_hi + ro * ROWB + kbyteb);
                bh[2 * p][0] = r4[0]; bh[2 * p][1] = r4[1];
                bh[2 * p + 1][0] = r4[2]; bh[2 * p + 1][1] = r4[3];
                ldsm4(r4, sB_lo + ro * ROWB + kbyteb);
                bl[2 * p][0] = r4[0]; bl[2 * p][1] = r4[1];
                bl[2 * p + 1][0] = r4[2]; bl[2 * p + 1][1] = r4[3];
            }
#pragma unroll
            for (int mt = 0; mt < 2; mt++)
#pragma unroll
                for (int nt = 0; nt < 8; nt++) {
                    mma16816(c[mt][nt], ah[mt], bh[nt]);
                    mma16816(c[mt][nt], ah[mt], bl[nt]);
                    mma16816(c[mt][nt], al[mt], bh[nt]);
                }
        }
        __syncthreads();
    }

    // ---- epilogue ----
#pragma unroll
    for (int mt = 0; mt < 2; mt++) {
#pragma unroll
        for (int nt = 0; nt < 8; nt++) {
            int col = n0 + warp_n * 64 + nt * 8 + (lane & 3) * 2;
#pragma unroll
            for (int half = 0; half < 2; half++) {
                int m = warp_m * 32 + mt * 16 + (lane >> 2) + half * 8;
                int en = ent[m];
                if (en < 0) continue;
                float v0 = c[mt][nt][half * 2 + 0] + bias[e * Ntot + col];
                float v1 = c[mt][nt][half * 2 + 1] + bias[e * Ntot + col + 1];
                if (MODE == 0) {
                    float ga = 0.5f * v0 * (1.0f + erff(v0 * 0.7071067811865476f));
                    float gb = 0.5f * v1 * (1.0f + erff(v1 * 0.7071067811865476f));
                    __nv_bfloat16 h0, l0, h1, l1;
                    split2(ga, h0, l0); split2(gb, h1, l1);
                    uint32_t ph = (uint32_t)__bfloat16_as_ushort(h0)
                        | ((uint32_t)__bfloat16_as_ushort(h1) << 16);
                    uint32_t pl = (uint32_t)__bfloat16_as_ushort(l0)
                        | ((uint32_t)__bfloat16_as_ushort(l1) << 16);
                    *(uint32_t*)(outh + (size_t)en * Hn + col) = ph;
                    *(uint32_t*)(outl + (size_t)en * Hn + col) = pl;
                } else {
                    float g = gw[m];
                    float2 o = make_float2(v0 * g, v1 * g);
                    *(float2*)(outf + (size_t)en * Dn + col) = o;
                }
            }
        }
    }
}

// ---------------- kernel: combine two slots into y -------------------------
__global__ void combine_kernel(float* __restrict__ y) {
    int i = blockIdx.x * 256 + threadIdx.x;
    if (i >= Nn * Dn / 4) return;
    int t = i / (Dn / 4);
    int cc = i % (Dn / 4);
    const float4* a = (const float4*)g_out;
    float4 v0 = a[(size_t)(2 * t) * (Dn / 4) + cc];
    float4 v1 = a[(size_t)(2 * t + 1) * (Dn / 4) + cc];
    float4 o;
    o.x = v0.x + v1.x; o.y = v0.y + v1.y; o.z = v0.z + v1.z; o.w = v0.w + v1.w;
    ((float4*)y)[i] = o;
}

// ---------------- launch ----------------------------------------------------
extern "C" void kernel_launch(void* const* d_in, const int* in_sizes, int n_in,
                              void* d_out, int out_size) {
    const float* x   = (const float*)d_in[0];
    const float* mus = (const float*)d_in[1];
    const float* ls  = (const float*)d_in[2];
    const float* W1  = (const float*)d_in[3];
    const float* b1  = (const float*)d_in[4];
    const float* W2  = (const float*)d_in[5];
    const float* b2  = (const float*)d_in[6];
    float* out = (float*)d_out;

    const int Ny  = Nn * Dn;
    const int Nlp = Nn * En;
    const int Nti = Nn * Kn;
    int has_lp = (out_size >= Ny + Nlp) ? 1 : 0;
    int has_ti = (out_size >= Ny + Nlp + Nti) ? 1 : 0;
    float* out_lp = out + Ny;
    float* out_ti = out + Ny + Nlp;

    precompute_kernel<<<Bn * En, 256>>>(ls);

    __nv_bfloat16 *w1h, *w1l, *w2h, *w2l, *hh, *hl;
    float* obuf;
    cudaGetSymbolAddress((void**)&w1h, g_w1h);
    cudaGetSymbolAddress((void**)&w1l, g_w1l);
    cudaGetSymbolAddress((void**)&w2h, g_w2h);
    cudaGetSymbolAddress((void**)&w2l, g_w2l);
    cudaGetSymbolAddress((void**)&hh, g_hh);
    cudaGetSymbolAddress((void**)&hl, g_hl);
    cudaGetSymbolAddress((void**)&obuf, g_out);

    // W1 [E][D][H] -> [E][H][D] split
    dim3 t1(Hn / 32, Dn / 32, En);
    transpose_split_kernel<<<t1, 256>>>(W1, w1h, w1l, Dn, Hn);
    // W2 [E][H][D] -> [E][D][H] split
    dim3 t2(Dn / 32, Hn / 32, En);
    transpose_split_kernel<<<t2, 256>>>(W2, w2h, w2l, Hn, Dn);

    gate_kernel<<<Nn / 8, 256>>>(x, mus, out_lp, out_ti, has_lp, has_ti);

    dim3 g1(Hn / 128, Nn / 128, En);   // (8, 64, 8), early-exit beyond counts
    gemm_mma<0><<<g1, 256>>>(x, nullptr, nullptr, w1h, w1l, b1, nullptr, hh, hl);

    dim3 g2(Dn / 128, Nn / 128, En);   // (4, 64, 8)
    gemm_mma<1><<<g2, 256>>>(nullptr, hh, hl, w2h, w2l, b2, obuf, nullptr, nullptr);

    combine_kernel<<<(Ny / 4 + 255) / 256, 256>>>(out);
    (void)in_sizes; (void)n_in;
}

// round 6
// speedup vs baseline: 4.7793x; 1.6725x over previous
#include <cuda_runtime.h>
#include <cuda_fp16.h>
#include <math.h>
#include <stdint.h>

// Problem dims
#define Bn 8
#define Tn 1024
#define Dn 512
#define Hn 1024
#define En 8
#define Kn 2
#define Nn (Bn * Tn)          // 8192 tokens
#define LOG_2PI 1.8378770664093453f

// ---------------- scratch (static __device__ globals) ----------------------
__device__ __half g_hh[(size_t)Nn * Kn * Hn];          // gelu(h) fp16, [slot][H]
__device__ __half g_xh[(size_t)Nn * Dn];               // x cast to fp16
__device__ float  g_out[(size_t)Nn * Kn * Dn];         // per-slot gated outputs
__device__ float  g_gate[Nn * Kn];
__device__ int    g_counts[En];
__device__ int    g_list[En][Nn];
__device__ float2 g_tab[Bn * En * Dn];                 // (isig2, mu*isig2)
__device__ float  g_C[Bn * En];                        // per-(b,e) constant
__device__ __half g_w1h[(size_t)En * Hn * Dn];         // W1^T [E][H][D] hi
__device__ __half g_w1l[(size_t)En * Hn * Dn];         // lo
__device__ __half g_w2h[(size_t)En * Dn * Hn];         // W2^T [E][D][H] hi
__device__ __half g_w2l[(size_t)En * Dn * Hn];

// ---------------- helpers ---------------------------------------------------
__device__ __forceinline__ uint32_t smem_u32(const void* p) {
    uint32_t a;
    asm("{ .reg .u64 t; cvta.to.shared.u64 t, %1; cvt.u32.u64 %0, t; }" : "=r"(a) : "l"(p));
    return a;
}
__device__ __forceinline__ void ldsm4(uint32_t* r, uint32_t addr) {
    asm volatile("ldmatrix.sync.aligned.m8n8.x4.shared.b16 {%0,%1,%2,%3}, [%4];"
        : "=r"(r[0]), "=r"(r[1]), "=r"(r[2]), "=r"(r[3]) : "r"(addr));
}
__device__ __forceinline__ void mma16816(float* c, const uint32_t* a, const uint32_t* b) {
    asm volatile("mma.sync.aligned.m16n8k16.row.col.f32.f16.f16.f32 "
        "{%0,%1,%2,%3}, {%4,%5,%6,%7}, {%8,%9}, {%0,%1,%2,%3};"
        : "+f"(c[0]), "+f"(c[1]), "+f"(c[2]), "+f"(c[3])
        : "r"(a[0]), "r"(a[1]), "r"(a[2]), "r"(a[3]), "r"(b[0]), "r"(b[1]));
}
#define CPA16(dst, src) asm volatile("cp.async.cg.shared.global [%0], [%1], 16;" :: "r"(dst), "l"(src) : "memory")
#define CPC()  asm volatile("cp.async.commit_group;" ::: "memory")
#define CPW1() asm volatile("cp.async.wait_group 1;" ::: "memory")
#define CPW0() asm volatile("cp.async.wait_group 0;" ::: "memory")

// ---------------- kernel: precompute gate table + zero counts --------------
__global__ void precompute_kernel(const float* __restrict__ log_sigmas,
                                  const float* __restrict__ mus) {
    int be = blockIdx.x;              // b*En + e
    int tid = threadIdx.x;            // 256
    if (be == 0 && tid < En) g_counts[tid] = 0;
    __shared__ float red[256];
    float s = 0.0f;
    for (int d = tid; d < Dn; d += 256) {
        float ls = log_sigmas[be * Dn + d];
        float mu = mus[be * Dn + d];
        float s2 = __expf(-2.0f * ls);
        g_tab[be * Dn + d] = make_float2(s2, mu * s2);
        s += -0.5f * mu * mu * s2 - ls;
    }
    red[tid] = s;
    __syncthreads();
    for (int o = 128; o > 0; o >>= 1) {
        if (tid < o) red[tid] += red[tid + o];
        __syncthreads();
    }
    if (tid == 0) g_C[be] = red[0] - 0.5f * LOG_2PI * (float)Dn;
}

// ---------------- kernel: cast x to fp16 ------------------------------------
__global__ void xcast_kernel(const float* __restrict__ x, __half* __restrict__ xh) {
    int i = blockIdx.x * 256 + threadIdx.x;
    if (i >= Nn * Dn / 4) return;
    float4 v = ((const float4*)x)[i];
    __half2 a = __floats2half2_rn(v.x, v.y);
    __half2 b = __floats2half2_rn(v.z, v.w);
    uint2 o;
    o.x = *(uint32_t*)&a; o.y = *(uint32_t*)&b;
    ((uint2*)xh)[i] = o;
}

// ---------------- kernel: transpose + fp16 hi/lo split ---------------------
// src [E][R][C] -> dst [E][C][R]
__global__ void transpose_split_kernel(const float* __restrict__ src,
                                       __half* __restrict__ dhi,
                                       __half* __restrict__ dlo,
                                       int R, int C) {
    __shared__ float t[32][33];
    int e = blockIdx.z;
    int c0 = blockIdx.x * 32, r0 = blockIdx.y * 32;
    int tx = threadIdx.x & 31, ty = threadIdx.x >> 5;
    const float* s = src + (size_t)e * R * C;
#pragma unroll
    for (int p = 0; p < 4; p++)
        t[ty + p * 8][tx] = s[(size_t)(r0 + ty + p * 8) * C + c0 + tx];
    __syncthreads();
#pragma unroll
    for (int p = 0; p < 4; p++) {
        float v = t[tx][ty + p * 8];
        __half hi = __float2half_rn(v);
        __half lo = __float2half_rn(v - __half2float(hi));
        size_t o = (size_t)e * C * R + (size_t)(c0 + ty + p * 8) * R + r0 + tx;
        dhi[o] = hi;
        dlo[o] = lo;
    }
}

// ---------------- kernel: gating (one warp per token, smem table) ----------
__global__ __launch_bounds__(256) void gate_kernel(const float* __restrict__ x,
                                                   float* __restrict__ out_lp,
                                                   float* __restrict__ out_ti,
                                                   int has_lp, int has_ti) {
    __shared__ float2 stab[En * Dn];   // 32 KB
    int tid = threadIdx.x;
    int warp = tid >> 5, lane = tid & 31;
    int t = blockIdx.x * 8 + warp;     // 8 tokens per CTA, same batch
    int b = blockIdx.x >> 7;           // 128 CTAs per batch

    for (int i = tid; i < En * Dn; i += 256) stab[i] = g_tab[b * En * Dn + i];
    __syncthreads();

    float xr[16], xr2[16];
#pragma unroll
    for (int i = 0; i < 16; i++) {
        xr[i] = x[t * Dn + lane + 32 * i];
        xr2[i] = xr[i] * xr[i];
    }

    float lp[En];
#pragma unroll
    for (int e = 0; e < En; e++) {
        const float2* tb = stab + e * Dn;
        float a1 = 0.0f, a2 = 0.0f;
#pragma unroll
        for (int i = 0; i < 16; i++) {
            float2 p = tb[lane + 32 * i];
            a1 = fmaf(xr2[i], p.x, a1);
            a2 = fmaf(xr[i], p.y, a2);
        }
        float sacc = a2 - 0.5f * a1;
#pragma unroll
        for (int o = 16; o > 0; o >>= 1) sacc += __shfl_xor_sync(0xffffffffu, sacc, o);
        lp[e] = sacc + g_C[b * En + e];
    }

    if (lane == 0) {
        int e0 = 0;
#pragma unroll
        for (int e = 1; e < En; e++) if (lp[e] > lp[e0]) e0 = e;
        int e1 = -1;
#pragma unroll
        for (int e = 0; e < En; e++) {
            if (e == e0) continue;
            if (e1 < 0 || lp[e] > lp[e1]) e1 = e;
        }
        float p1 = __expf(lp[e1] - lp[e0]);
        float inv = 1.0f / (1.0f + p1);
        g_gate[t * 2 + 0] = inv;
        g_gate[t * 2 + 1] = p1 * inv;
        int p = atomicAdd(&g_counts[e0], 1);
        g_list[e0][p] = (t << 1) | 0;
        p = atomicAdd(&g_counts[e1], 1);
        g_list[e1][p] = (t << 1) | 1;
        if (has_lp) {
#pragma unroll
            for (int e = 0; e < En; e++) out_lp[t * En + e] = lp[e];
        }
        if (has_ti) {
            out_ti[t * 2 + 0] = (float)e0;
            out_ti[t * 2 + 1] = (float)e1;
        }
    }
}

// ---------------- warp-MMA grouped GEMM, cp.async double-buffered -----------
// CTA 128x128, 8 warps (warp tile 32x64), K-step 32.
// A fp16 (single), B fp16 hi+lo: out = Ah*Bh + Ah*Bl.
// MODE 0: h = gelu(xh @ W1T + b1) -> g_hh fp16. K=512, N=1024, A row = en>>1.
// MODE 1: g_out = gate*(g_hh @ W2T + b2). K=1024, N=512, A row = en.
#define ROWB 80
#define STG_BYTES (3 * 128 * ROWB)    // A + Bh + Bl per stage = 30720
template <int MODE>
__global__ __launch_bounds__(256) void gemm_mma(const __half* __restrict__ Aglob,
                                                const __half* __restrict__ Bhg,
                                                const __half* __restrict__ Blg,
                                                const float* __restrict__ bias,
                                                float* __restrict__ outf,
                                                __half* __restrict__ outh) {
    constexpr int Ktot = MODE ? Hn : Dn;
    constexpr int Ntot = MODE ? Dn : Hn;
    constexpr int NCH = Ktot / 32;

    int e = blockIdx.z;
    int cnt = g_counts[e];
    int row0 = blockIdx.y * 128;
    if (row0 >= cnt) return;
    int n0 = blockIdx.x * 128;

    extern __shared__ char sdyn[];
    __shared__ int ent[128];
    __shared__ int rowIdx[128];
    __shared__ float gw[128];

    int tid = threadIdx.x, lane = tid & 31, wid = tid >> 5;
    int warp_m = wid & 3, warp_n = wid >> 2;

    if (tid < 128) {
        int en = (row0 + tid < cnt) ? g_list[e][row0 + tid] : -1;
        ent[tid] = en;
        gw[tid] = (en >= 0) ? g_gate[en] : 0.0f;
        int safe = g_list[e][row0];              // always valid (row0 < cnt)
        int use = (en >= 0) ? en : safe;
        rowIdx[tid] = MODE ? use : (use >> 1);
    }
    __syncthreads();

    const __half* Bhe = Bhg + (size_t)e * Ntot * Ktot + (size_t)n0 * Ktot;
    const __half* Ble = Blg + (size_t)e * Ntot * Ktot + (size_t)n0 * Ktot;
    uint32_t sbase = smem_u32(sdyn);

    float c[2][8][4];
#pragma unroll
    for (int i = 0; i < 2; i++)
#pragma unroll
        for (int j = 0; j < 8; j++)
#pragma unroll
            for (int q = 0; q < 4; q++) c[i][j][q] = 0.0f;

    uint32_t a_row = (uint32_t)(lane & 15);
    uint32_t a_kh  = (uint32_t)((lane >> 4) << 3);
    uint32_t b_row = (uint32_t)((lane & 7) + ((lane >> 4) << 3));
    uint32_t b_kh  = (uint32_t)(lane & 8);

    // per-thread prefetch assignments (2 chunks of A, 2 of Bh, 2 of Bl)
    auto prefetch = [&](int k0, int s) {
        uint32_t base = sbase + s * STG_BYTES;
#pragma unroll
        for (int j = 0; j < 2; j++) {
            int i = tid + 256 * j;
            int m = i >> 2, cc = i & 3;
            const __half* src = Aglob + (size_t)rowIdx[m] * Ktot + k0 + cc * 8;
            CPA16(base + m * ROWB + cc * 16, src);
        }
#pragma unroll
        for (int j = 0; j < 2; j++) {
            int i = tid + 256 * j;
            int n = i >> 2, cc = i & 3;
            CPA16(base + 128 * ROWB + n * ROWB + cc * 16, Bhe + (size_t)n * Ktot + k0 + cc * 8);
            CPA16(base + 2 * 128 * ROWB + n * ROWB + cc * 16, Ble + (size_t)n * Ktot + k0 + cc * 8);
        }
    };

    prefetch(0, 0);
    CPC();

    for (int cc = 0; cc < NCH; cc++) {
        int s = cc & 1;
        if (cc + 1 < NCH) { prefetch((cc + 1) * 32, s ^ 1); CPC(); CPW1(); }
        else CPW0();
        __syncthreads();

        uint32_t baseA = sbase + s * STG_BYTES;
        uint32_t baseBh = baseA + 128 * ROWB;
        uint32_t baseBl = baseBh + 128 * ROWB;
#pragma unroll
        for (int kk = 0; kk < 2; kk++) {
            uint32_t ka = (uint32_t)(kk * 32) + a_kh * 2;
            uint32_t ah[2][4];
#pragma unroll
            for (int mt = 0; mt < 2; mt++) {
                uint32_t ro = (uint32_t)(warp_m * 32 + mt * 16) + a_row;
                ldsm4(ah[mt], baseA + ro * ROWB + ka);
            }
            uint32_t kb = (uint32_t)(kk * 32) + b_kh * 2;
            uint32_t bh[8][2], bl[8][2];
#pragma unroll
            for (int p = 0; p < 4; p++) {
                uint32_t ro = (uint32_t)(warp_n * 64 + p * 16) + b_row;
                uint32_t r4[4];
                ldsm4(r4, baseBh + ro * ROWB + kb);
                bh[2 * p][0] = r4[0]; bh[2 * p][1] = r4[1];
                bh[2 * p + 1][0] = r4[2]; bh[2 * p + 1][1] = r4[3];
                ldsm4(r4, baseBl + ro * ROWB + kb);
                bl[2 * p][0] = r4[0]; bl[2 * p][1] = r4[1];
                bl[2 * p + 1][0] = r4[2]; bl[2 * p + 1][1] = r4[3];
            }
#pragma unroll
            for (int mt = 0; mt < 2; mt++)
#pragma unroll
                for (int nt = 0; nt < 8; nt++) {
                    mma16816(c[mt][nt], ah[mt], bh[nt]);
                    mma16816(c[mt][nt], ah[mt], bl[nt]);
                }
        }
        __syncthreads();
    }

    // ---- epilogue ----
#pragma unroll
    for (int mt = 0; mt < 2; mt++) {
#pragma unroll
        for (int nt = 0; nt < 8; nt++) {
            int col = n0 + warp_n * 64 + nt * 8 + (lane & 3) * 2;
#pragma unroll
            for (int half = 0; half < 2; half++) {
                int m = warp_m * 32 + mt * 16 + (lane >> 2) + half * 8;
                int en = ent[m];
                if (en < 0) continue;
                float v0 = c[mt][nt][half * 2 + 0] + bias[e * Ntot + col];
                float v1 = c[mt][nt][half * 2 + 1] + bias[e * Ntot + col + 1];
                if (MODE == 0) {
                    float ga = 0.5f * v0 * (1.0f + erff(v0 * 0.7071067811865476f));
                    float gb = 0.5f * v1 * (1.0f + erff(v1 * 0.7071067811865476f));
                    __half2 h2 = __floats2half2_rn(ga, gb);
                    *(uint32_t*)(outh + (size_t)en * Hn + col) = *(uint32_t*)&h2;
                } else {
                    float g = gw[m];
                    float2 o = make_float2(v0 * g, v1 * g);
                    *(float2*)(outf + (size_t)en * Dn + col) = o;
                }
            }
        }
    }
}

// ---------------- kernel: combine two slots into y -------------------------
__global__ void combine_kernel(float* __restrict__ y) {
    int i = blockIdx.x * 256 + threadIdx.x;
    if (i >= Nn * Dn / 4) return;
    int t = i / (Dn / 4);
    int cc = i % (Dn / 4);
    const float4* a = (const float4*)g_out;
    float4 v0 = a[(size_t)(2 * t) * (Dn / 4) + cc];
    float4 v1 = a[(size_t)(2 * t + 1) * (Dn / 4) + cc];
    float4 o;
    o.x = v0.x + v1.x; o.y = v0.y + v1.y; o.z = v0.z + v1.z; o.w = v0.w + v1.w;
    ((float4*)y)[i] = o;
}

// ---------------- launch ----------------------------------------------------
extern "C" void kernel_launch(void* const* d_in, const int* in_sizes, int n_in,
                              void* d_out, int out_size) {
    const float* x   = (const float*)d_in[0];
    const float* mus = (const float*)d_in[1];
    const float* ls  = (const float*)d_in[2];
    const float* W1  = (const float*)d_in[3];
    const float* b1  = (const float*)d_in[4];
    const float* W2  = (const float*)d_in[5];
    const float* b2  = (const float*)d_in[6];
    float* out = (float*)d_out;

    const int Ny  = Nn * Dn;
    const int Nlp = Nn * En;
    const int Nti = Nn * Kn;
    int has_lp = (out_size >= Ny + Nlp) ? 1 : 0;
    int has_ti = (out_size >= Ny + Nlp + Nti) ? 1 : 0;
    float* out_lp = out + Ny;
    float* out_ti = out + Ny + Nlp;

    static int smem_set = 0;
    if (!smem_set) {
        cudaFuncSetAttribute(gemm_mma<0>, cudaFuncAttributeMaxDynamicSharedMemorySize, 2 * STG_BYTES);
        cudaFuncSetAttribute(gemm_mma<1>, cudaFuncAttributeMaxDynamicSharedMemorySize, 2 * STG_BYTES);
        smem_set = 1;
    }

    precompute_kernel<<<Bn * En, 256>>>(ls, mus);

    __half *w1h, *w1l, *w2h, *w2l, *hh, *xh;
    float* obuf;
    cudaGetSymbolAddress((void**)&w1h, g_w1h);
    cudaGetSymbolAddress((void**)&w1l, g_w1l);
    cudaGetSymbolAddress((void**)&w2h, g_w2h);
    cudaGetSymbolAddress((void**)&w2l, g_w2l);
    cudaGetSymbolAddress((void**)&hh, g_hh);
    cudaGetSymbolAddress((void**)&xh, g_xh);
    cudaGetSymbolAddress((void**)&obuf, g_out);

    xcast_kernel<<<(Ny / 4 + 255) / 256, 256>>>(x, xh);

    dim3 t1(Hn / 32, Dn / 32, En);
    transpose_split_kernel<<<t1, 256>>>(W1, w1h, w1l, Dn, Hn);
    dim3 t2(Dn / 32, Hn / 32, En);
    transpose_split_kernel<<<t2, 256>>>(W2, w2h, w2l, Hn, Dn);

    gate_kernel<<<Nn / 8, 256>>>(x, out_lp, out_ti, has_lp, has_ti);

    dim3 g1(Hn / 128, Nn / 128, En);
    gemm_mma<0><<<g1, 256, 2 * STG_BYTES>>>(xh, w1h, w1l, b1, nullptr, hh);

    dim3 g2(Dn / 128, Nn / 128, En);
    gemm_mma<1><<<g2, 256, 2 * STG_BYTES>>>(hh, w2h, w2l, b2, obuf, nullptr);

    combine_kernel<<<(Ny / 4 + 255) / 256, 256>>>(out);
    (void)in_sizes; (void)n_in;
}

// round 7
// speedup vs baseline: 4.8292x; 1.0105x over previous
#include <cuda_runtime.h>
#include <cuda_fp16.h>
#include <math.h>
#include <stdint.h>

// Problem dims
#define Bn 8
#define Tn 1024
#define Dn 512
#define Hn 1024
#define En 8
#define Kn 2
#define Nn (Bn * Tn)          // 8192 tokens
#define LOG_2PI 1.8378770664093453f

// ---------------- scratch (static __device__ globals) ----------------------
__device__ __half g_hh[(size_t)Nn * Kn * Hn];          // gelu(h) fp16, [slot][H]
__device__ __half g_xh[(size_t)Nn * Dn];               // x cast to fp16
__device__ float  g_out[(size_t)Nn * Kn * Dn];         // per-slot gated outputs
__device__ float  g_gate[Nn * Kn];
__device__ int    g_counts[En];
__device__ int    g_list[En][Nn];
__device__ float2 g_tab[Bn * En * Dn];                 // (isig2, mu*isig2)
__device__ float  g_C[Bn * En];                        // per-(b,e) constant
__device__ __half g_w1h[(size_t)En * Hn * Dn];         // W1^T [E][H][D] hi
__device__ __half g_w1l[(size_t)En * Hn * Dn];         // lo
__device__ __half g_w2h[(size_t)En * Dn * Hn];         // W2^T [E][D][H] hi
__device__ __half g_w2l[(size_t)En * Dn * Hn];

// ---------------- helpers ---------------------------------------------------
__device__ __forceinline__ uint32_t smem_u32(const void* p) {
    uint32_t a;
    asm("{ .reg .u64 t; cvta.to.shared.u64 t, %1; cvt.u32.u64 %0, t; }" : "=r"(a) : "l"(p));
    return a;
}
__device__ __forceinline__ void ldsm4(uint32_t* r, uint32_t addr) {
    asm volatile("ldmatrix.sync.aligned.m8n8.x4.shared.b16 {%0,%1,%2,%3}, [%4];"
        : "=r"(r[0]), "=r"(r[1]), "=r"(r[2]), "=r"(r[3]) : "r"(addr));
}
__device__ __forceinline__ void mma16816(float* c, const uint32_t* a, const uint32_t* b) {
    asm volatile("mma.sync.aligned.m16n8k16.row.col.f32.f16.f16.f32 "
        "{%0,%1,%2,%3}, {%4,%5,%6,%7}, {%8,%9}, {%0,%1,%2,%3};"
        : "+f"(c[0]), "+f"(c[1]), "+f"(c[2]), "+f"(c[3])
        : "r"(a[0]), "r"(a[1]), "r"(a[2]), "r"(a[3]), "r"(b[0]), "r"(b[1]));
}
#define CPA16(dst, src) asm volatile("cp.async.cg.shared.global [%0], [%1], 16;" :: "r"(dst), "l"(src) : "memory")
#define CPC()  asm volatile("cp.async.commit_group;" ::: "memory")
#define CPW2() asm volatile("cp.async.wait_group 2;" ::: "memory")
#define CPW1() asm volatile("cp.async.wait_group 1;" ::: "memory")
#define CPW0() asm volatile("cp.async.wait_group 0;" ::: "memory")

// ---------------- kernel: precompute gate table + zero counts --------------
__global__ void precompute_kernel(const float* __restrict__ log_sigmas,
                                  const float* __restrict__ mus) {
    int be = blockIdx.x;              // b*En + e
    int tid = threadIdx.x;            // 256
    if (be == 0 && tid < En) g_counts[tid] = 0;
    __shared__ float red[256];
    float s = 0.0f;
    for (int d = tid; d < Dn; d += 256) {
        float ls = log_sigmas[be * Dn + d];
        float mu = mus[be * Dn + d];
        float s2 = __expf(-2.0f * ls);
        g_tab[be * Dn + d] = make_float2(s2, mu * s2);
        s += -0.5f * mu * mu * s2 - ls;
    }
    red[tid] = s;
    __syncthreads();
    for (int o = 128; o > 0; o >>= 1) {
        if (tid < o) red[tid] += red[tid + o];
        __syncthreads();
    }
    if (tid == 0) g_C[be] = red[0] - 0.5f * LOG_2PI * (float)Dn;
}

// ---------------- kernel: transpose + fp16 hi/lo split ---------------------
// src [E][R][C] fp32 -> dst [E][C][R] half. Tiles 64R x 32C, coalesced half2 out.
__global__ __launch_bounds__(256) void transpose_split_kernel(
        const float* __restrict__ src,
        __half* __restrict__ dhi,
        __half* __restrict__ dlo,
        int R, int C) {
    __shared__ float t[64][33];
    int e = blockIdx.z;
    int c0 = blockIdx.x * 32, r0 = blockIdx.y * 64;
    int tid = threadIdx.x;
    const float* s = src + (size_t)e * R * C;
#pragma unroll
    for (int p = 0; p < 8; p++) {
        int i = tid + p * 256;
        int r = i >> 5, c = i & 31;
        t[r][c] = s[(size_t)(r0 + r) * C + c0 + c];
    }
    __syncthreads();
    size_t obase = (size_t)e * C * R + r0;
#pragma unroll
    for (int p = 0; p < 4; p++) {
        int i = tid + p * 256;
        int oc = i >> 5, j = i & 31;        // output row oc (C), col pair 2j (R)
        float v0 = t[2 * j][oc];
        float v1 = t[2 * j + 1][oc];
        __half h0 = __float2half_rn(v0);
        __half h1 = __float2half_rn(v1);
        __half l0 = __float2half_rn(v0 - __half2float(h0));
        __half l1 = __float2half_rn(v1 - __half2float(h1));
        uint32_t ph = (uint32_t)*(uint16_t*)&h0 | ((uint32_t)*(uint16_t*)&h1 << 16);
        uint32_t pl = (uint32_t)*(uint16_t*)&l0 | ((uint32_t)*(uint16_t*)&l1 << 16);
        size_t o = obase + (size_t)(c0 + oc) * R + 2 * j;
        *(uint32_t*)(dhi + o) = ph;
        *(uint32_t*)(dlo + o) = pl;
    }
}

// ---------------- kernel: gating + fused x->fp16 cast ----------------------
__global__ __launch_bounds__(256) void gate_kernel(const float* __restrict__ x,
                                                   __half* __restrict__ xh,
                                                   float* __restrict__ out_lp,
                                                   float* __restrict__ out_ti,
                                                   int has_lp, int has_ti) {
    __shared__ float2 stab[En * Dn];   // 32 KB
    int tid = threadIdx.x;
    int warp = tid >> 5, lane = tid & 31;
    int t = blockIdx.x * 8 + warp;     // 8 tokens per CTA, same batch
    int b = blockIdx.x >> 7;           // 128 CTAs per batch

    for (int i = tid; i < En * Dn; i += 256) stab[i] = g_tab[b * En * Dn + i];
    __syncthreads();

    float xr[16], xr2[16];
#pragma unroll
    for (int i = 0; i < 16; i++) {
        xr[i] = x[t * Dn + lane + 32 * i];
        xr2[i] = xr[i] * xr[i];
    }
    // fused fp16 cast (lane-contiguous, coalesced 64B per instr)
#pragma unroll
    for (int i = 0; i < 16; i++)
        xh[t * Dn + lane + 32 * i] = __float2half_rn(xr[i]);

    float lp[En];
#pragma unroll
    for (int e = 0; e < En; e++) {
        const float2* tb = stab + e * Dn;
        float a1 = 0.0f, a2 = 0.0f;
#pragma unroll
        for (int i = 0; i < 16; i++) {
            float2 p = tb[lane + 32 * i];
            a1 = fmaf(xr2[i], p.x, a1);
            a2 = fmaf(xr[i], p.y, a2);
        }
        float sacc = a2 - 0.5f * a1;
#pragma unroll
        for (int o = 16; o > 0; o >>= 1) sacc += __shfl_xor_sync(0xffffffffu, sacc, o);
        lp[e] = sacc + g_C[b * En + e];
    }

    if (lane == 0) {
        int e0 = 0;
#pragma unroll
        for (int e = 1; e < En; e++) if (lp[e] > lp[e0]) e0 = e;
        int e1 = -1;
#pragma unroll
        for (int e = 0; e < En; e++) {
            if (e == e0) continue;
            if (e1 < 0 || lp[e] > lp[e1]) e1 = e;
        }
        float p1 = __expf(lp[e1] - lp[e0]);
        float inv = 1.0f / (1.0f + p1);
        g_gate[t * 2 + 0] = inv;
        g_gate[t * 2 + 1] = p1 * inv;
        int p = atomicAdd(&g_counts[e0], 1);
        g_list[e0][p] = (t << 1) | 0;
        p = atomicAdd(&g_counts[e1], 1);
        g_list[e1][p] = (t << 1) | 1;
        if (has_lp) {
#pragma unroll
            for (int e = 0; e < En; e++) out_lp[t * En + e] = lp[e];
        }
        if (has_ti) {
            out_ti[t * 2 + 0] = (float)e0;
            out_ti[t * 2 + 1] = (float)e1;
        }
    }
}

// ---------------- warp-MMA grouped GEMM, 3-stage cp.async pipeline ---------
// CTA 128x128, 8 warps (warp tile 32x64), K-step 32.
// A fp16 single, B fp16 hi+lo: out = Ah*Bh + Ah*Bl.
// MODE 0: h = gelu(xh @ W1T + b1) -> g_hh fp16. K=512, N=1024, A row = en>>1.
// MODE 1: g_out = gate*(g_hh @ W2T + b2). K=1024, N=512, A row = en.
#define ROWB 80
#define STG_BYTES (3 * 128 * ROWB)    // A + Bh + Bl per stage = 30720
#define NSTG 3
template <int MODE>
__global__ __launch_bounds__(256) void gemm_mma(const __half* __restrict__ Aglob,
                                                const __half* __restrict__ Bhg,
                                                const __half* __restrict__ Blg,
                                                const float* __restrict__ bias,
                                                float* __restrict__ outf,
                                                __half* __restrict__ outh) {
    constexpr int Ktot = MODE ? Hn : Dn;
    constexpr int Ntot = MODE ? Dn : Hn;
    constexpr int NCH = Ktot / 32;

    int e = blockIdx.z;
    int cnt = g_counts[e];
    int row0 = blockIdx.y * 128;
    if (row0 >= cnt) return;
    int n0 = blockIdx.x * 128;

    extern __shared__ char sdyn[];
    __shared__ int ent[128];
    __shared__ int rowIdx[128];
    __shared__ float gw[128];

    int tid = threadIdx.x, lane = tid & 31, wid = tid >> 5;
    int warp_m = wid & 3, warp_n = wid >> 2;

    if (tid < 128) {
        int en = (row0 + tid < cnt) ? g_list[e][row0 + tid] : -1;
        ent[tid] = en;
        gw[tid] = (en >= 0) ? g_gate[en] : 0.0f;
        int safe = g_list[e][row0];
        int use = (en >= 0) ? en : safe;
        rowIdx[tid] = MODE ? use : (use >> 1);
    }
    __syncthreads();

    const __half* Bhe = Bhg + (size_t)e * Ntot * Ktot + (size_t)n0 * Ktot;
    const __half* Ble = Blg + (size_t)e * Ntot * Ktot + (size_t)n0 * Ktot;
    uint32_t sbase = smem_u32(sdyn);

    float c[2][8][4];
#pragma unroll
    for (int i = 0; i < 2; i++)
#pragma unroll
        for (int j = 0; j < 8; j++)
#pragma unroll
            for (int q = 0; q < 4; q++) c[i][j][q] = 0.0f;

    uint32_t a_row = (uint32_t)(lane & 15);
    uint32_t a_kh  = (uint32_t)((lane >> 4) << 3);
    uint32_t b_row = (uint32_t)((lane & 7) + ((lane >> 4) << 3));
    uint32_t b_kh  = (uint32_t)(lane & 8);

    auto prefetch = [&](int k0, int s) {
        uint32_t base = sbase + s * STG_BYTES;
#pragma unroll
        for (int j = 0; j < 2; j++) {
            int i = tid + 256 * j;
            int m = i >> 2, cc = i & 3;
            const __half* src = Aglob + (size_t)rowIdx[m] * Ktot + k0 + cc * 8;
            CPA16(base + m * ROWB + cc * 16, src);
        }
#pragma unroll
        for (int j = 0; j < 2; j++) {
            int i = tid + 256 * j;
            int n = i >> 2, cc = i & 3;
            CPA16(base + 128 * ROWB + n * ROWB + cc * 16, Bhe + (size_t)n * Ktot + k0 + cc * 8);
            CPA16(base + 2 * 128 * ROWB + n * ROWB + cc * 16, Ble + (size_t)n * Ktot + k0 + cc * 8);
        }
    };

    prefetch(0, 0);
    CPC();
    prefetch(32, 1);
    CPC();

    for (int cc = 0; cc < NCH; cc++) {
        int s = cc % NSTG;
        if (cc + 2 < NCH) {
            prefetch((cc + 2) * 32, (cc + 2) % NSTG);
            CPC();
            CPW2();
        } else if (cc + 1 < NCH) {
            CPW1();
        } else {
            CPW0();
        }
        __syncthreads();

        uint32_t baseA = sbase + s * STG_BYTES;
        uint32_t baseBh = baseA + 128 * ROWB;
        uint32_t baseBl = baseBh + 128 * ROWB;
#pragma unroll
        for (int kk = 0; kk < 2; kk++) {
            uint32_t ka = (uint32_t)(kk * 32) + a_kh * 2;
            uint32_t ah[2][4];
#pragma unroll
            for (int mt = 0; mt < 2; mt++) {
                uint32_t ro = (uint32_t)(warp_m * 32 + mt * 16) + a_row;
                ldsm4(ah[mt], baseA + ro * ROWB + ka);
            }
            uint32_t kb = (uint32_t)(kk * 32) + b_kh * 2;
            uint32_t bh[8][2], bl[8][2];
#pragma unroll
            for (int p = 0; p < 4; p++) {
                uint32_t ro = (uint32_t)(warp_n * 64 + p * 16) + b_row;
                uint32_t r4[4];
                ldsm4(r4, baseBh + ro * ROWB + kb);
                bh[2 * p][0] = r4[0]; bh[2 * p][1] = r4[1];
                bh[2 * p + 1][0] = r4[2]; bh[2 * p + 1][1] = r4[3];
                ldsm4(r4, baseBl + ro * ROWB + kb);
                bl[2 * p][0] = r4[0]; bl[2 * p][1] = r4[1];
                bl[2 * p + 1][0] = r4[2]; bl[2 * p + 1][1] = r4[3];
            }
#pragma unroll
            for (int mt = 0; mt < 2; mt++)
#pragma unroll
                for (int nt = 0; nt < 8; nt++) {
                    mma16816(c[mt][nt], ah[mt], bh[nt]);
                    mma16816(c[mt][nt], ah[mt], bl[nt]);
                }
        }
        __syncthreads();
    }

    // ---- epilogue ----
#pragma unroll
    for (int mt = 0; mt < 2; mt++) {
#pragma unroll
        for (int nt = 0; nt < 8; nt++) {
            int col = n0 + warp_n * 64 + nt * 8 + (lane & 3) * 2;
#pragma unroll
            for (int half = 0; half < 2; half++) {
                int m = warp_m * 32 + mt * 16 + (lane >> 2) + half * 8;
                int en = ent[m];
                if (en < 0) continue;
                float v0 = c[mt][nt][half * 2 + 0] + bias[e * Ntot + col];
                float v1 = c[mt][nt][half * 2 + 1] + bias[e * Ntot + col + 1];
                if (MODE == 0) {
                    float ga = 0.5f * v0 * (1.0f + erff(v0 * 0.7071067811865476f));
                    float gb = 0.5f * v1 * (1.0f + erff(v1 * 0.7071067811865476f));
                    __half2 h2 = __floats2half2_rn(ga, gb);
                    *(uint32_t*)(outh + (size_t)en * Hn + col) = *(uint32_t*)&h2;
                } else {
                    float g = gw[m];
                    float2 o = make_float2(v0 * g, v1 * g);
                    *(float2*)(outf + (size_t)en * Dn + col) = o;
                }
            }
        }
    }
}

// ---------------- kernel: combine two slots into y -------------------------
__global__ void combine_kernel(float* __restrict__ y) {
    int i = blockIdx.x * 256 + threadIdx.x;
    if (i >= Nn * Dn / 4) return;
    int t = i / (Dn / 4);
    int cc = i % (Dn / 4);
    const float4* a = (const float4*)g_out;
    float4 v0 = a[(size_t)(2 * t) * (Dn / 4) + cc];
    float4 v1 = a[(size_t)(2 * t + 1) * (Dn / 4) + cc];
    float4 o;
    o.x = v0.x + v1.x; o.y = v0.y + v1.y; o.z = v0.z + v1.z; o.w = v0.w + v1.w;
    ((float4*)y)[i] = o;
}

// ---------------- launch ----------------------------------------------------
extern "C" void kernel_launch(void* const* d_in, const int* in_sizes, int n_in,
                              void* d_out, int out_size) {
    const float* x   = (const float*)d_in[0];
    const float* mus = (const float*)d_in[1];
    const float* ls  = (const float*)d_in[2];
    const float* W1  = (const float*)d_in[3];
    const float* b1  = (const float*)d_in[4];
    const float* W2  = (const float*)d_in[5];
    const float* b2  = (const float*)d_in[6];
    float* out = (float*)d_out;

    const int Ny  = Nn * Dn;
    const int Nlp = Nn * En;
    const int Nti = Nn * Kn;
    int has_lp = (out_size >= Ny + Nlp) ? 1 : 0;
    int has_ti = (out_size >= Ny + Nlp + Nti) ? 1 : 0;
    float* out_lp = out + Ny;
    float* out_ti = out + Ny + Nlp;

    cudaFuncSetAttribute(gemm_mma<0>, cudaFuncAttributeMaxDynamicSharedMemorySize, NSTG * STG_BYTES);
    cudaFuncSetAttribute(gemm_mma<1>, cudaFuncAttributeMaxDynamicSharedMemorySize, NSTG * STG_BYTES);

    precompute_kernel<<<Bn * En, 256>>>(ls, mus);

    __half *w1h, *w1l, *w2h, *w2l, *hh, *xh;
    float* obuf;
    cudaGetSymbolAddress((void**)&w1h, g_w1h);
    cudaGetSymbolAddress((void**)&w1l, g_w1l);
    cudaGetSymbolAddress((void**)&w2h, g_w2h);
    cudaGetSymbolAddress((void**)&w2l, g_w2l);
    cudaGetSymbolAddress((void**)&hh, g_hh);
    cudaGetSymbolAddress((void**)&xh, g_xh);
    cudaGetSymbolAddress((void**)&obuf, g_out);

    // W1 [E][D][H] -> [E][H][D] split: R=Dn, C=Hn
    dim3 t1(Hn / 32, Dn / 64, En);
    transpose_split_kernel<<<t1, 256>>>(W1, w1h, w1l, Dn, Hn);
    // W2 [E][H][D] -> [E][D][H] split: R=Hn, C=Dn
    dim3 t2(Dn / 32, Hn / 64, En);
    transpose_split_kernel<<<t2, 256>>>(W2, w2h, w2l, Hn, Dn);

    gate_kernel<<<Nn / 8, 256>>>(x, xh, out_lp, out_ti, has_lp, has_ti);

    dim3 g1(Hn / 128, Nn / 128, En);
    gemm_mma<0><<<g1, 256, NSTG * STG_BYTES>>>(xh, w1h, w1l, b1, nullptr, hh);

    dim3 g2(Dn / 128, Nn / 128, En);
    gemm_mma<1><<<g2, 256, NSTG * STG_BYTES>>>(hh, w2h, w2l, b2, obuf, nullptr);

    combine_kernel<<<(Ny / 4 + 255) / 256, 256>>>(out);
    (void)in_sizes; (void)n_in;
}